// round 6
// baseline (speedup 1.0000x reference)
#include <cuda_runtime.h>
#include <math.h>

#define T_STEPS 256
#define BB      32
#define NI      28
#define NH      1024
#define NO      10
#define GRID    128
#define NTH     512
#define NW      16        // warps per CTA
#define KS      64        // j-slice per warp
#define IT      32        // rows (i) per CTA
#define NBT     4         // batch tiles
#define CB      16        // V columns per CTA (8 batches x {cos,sin})
#define TWO_PI_F 6.283185307179586f
#define INV_TWO_PI_F 0.15915494309189535f

typedef unsigned long long ull;

// ---- persistent device scratch ----
__device__ float d_P[(size_t)T_STEPS * NH * BB];    // [t][h][b]
__device__ float d_V[2][NBT][NH][CB];               // [ping][btile][j][col]
__device__ float d_state[BB * NH];                  // [b][h]
__device__ unsigned g_bar4[NBT * 32];               // per-group counters, 128B apart
__device__ unsigned g_bar;                          // final one-shot barrier

// packed f32x2 helpers
#define PACK2(d,a,b) asm("mov.b64 %0, {%1, %2};" : "=l"(d) : "f"(a), "f"(b))
#define FMA2(d,a,b,c) asm("fma.rn.f32x2 %0, %1, %2, %3;" : "=l"(d) : "l"(a), "l"(b), "l"(c))
#define ADD2(d,a,b)  asm("add.rn.f32x2 %0, %1, %2;" : "=l"(d) : "l"(a), "l"(b))

// ---------------- prep ----------------
__global__ void prep_kernel(const float* __restrict__ x,
                            const float* __restrict__ Wi_w,
                            const float* __restrict__ Wi_b,
                            const float* __restrict__ omega) {
    const int bid = blockIdx.x;          // = t*BB + b
    const int t = bid >> 5;
    const int b = bid & 31;
    __shared__ float xs[NI];
    if (threadIdx.x < NI) xs[threadIdx.x] = x[(size_t)bid * NI + threadIdx.x];
    if (bid == 0) {
        if (threadIdx.x == 0) g_bar = 0u;
        if (threadIdx.x < NBT * 32) g_bar4[threadIdx.x] = 0u;
    }
    // init V ping buffer for state0 = 0: cos = 1 (even cols), sin = 0 (odd cols)
    if (bid < (NBT * NH * CB) / 256) {
        const int idx = bid * 256 + threadIdx.x;
        ((float*)d_V)[idx] = (idx & 1) ? 0.0f : 1.0f;
    }
    __syncthreads();
#pragma unroll
    for (int k = 0; k < NH / 256; ++k) {
        const int h = threadIdx.x + k * 256;
        float acc = Wi_b[h] + omega[h];
        const float* wr = Wi_w + (size_t)h * NI;
#pragma unroll
        for (int i = 0; i < NI; ++i) acc = fmaf(xs[i], wr[i], acc);
        d_P[((size_t)t * NH + h) * BB + b] = acc;
    }
}

// ---------------- proven atomic+spin barrier ----------------
__device__ __forceinline__ void bar_on(unsigned* ctr, unsigned target) {
    __syncthreads();
    if (threadIdx.x == 0) {
        __threadfence();
        atomicAdd(ctr, 1u);
        while (*(volatile unsigned*)ctr < target) { }
        __threadfence();
    }
    __syncthreads();
}

// ---------------- persistent scan kernel ----------------
// smem: WhT [1024][32] (128KB) | Vs [1024][16] (64KB) | red ull[16][16][16] swizzled (32KB) | redF ull[16][16] (2KB)
#define SMEM_FLOATS (NH*IT + NH*CB)
#define SMEM_BYTES  (SMEM_FLOATS*4 + NW*16*16*8 + 16*16*8)

extern __shared__ float smem[];

__global__ void __launch_bounds__(NTH, 1)
scan_kernel(const float* __restrict__ Wh,
            const float* __restrict__ W_out,
            const float* __restrict__ b_out,
            float* __restrict__ out) {
    float* WhT = smem;                          // WhT[j*32 + r] = Wh[i0+r][j]
    float* Vs  = smem + NH * IT;                // Vs[j*16 + c]
    ull*   red  = (ull*)(smem + SMEM_FLOATS);   // red[(w*16+RP)*16 + ((col+RP)&15)]
    ull*   redF = red + NW * 16 * 16;           // redF[RP*16 + col]

    const int tid = threadIdx.x;
    const int cta = blockIdx.x;
    const int it  = cta >> 2;            // i-tile 0..31
    const int bt  = cta & 3;             // batch-tile 0..3
    const int i0  = it * IT;

    // one-time fill of WhT (coalesced global reads)
    for (int idx = tid; idx < NH * IT; idx += NTH) {
        const int r = idx >> 10, j = idx & 1023;
        WhT[j * IT + r] = Wh[(size_t)(i0 + r) * NH + j];
    }

    const int w  = tid >> 5;             // warp: K-slice [w*64, w*64+64)
    const int l  = tid & 31;
    const int rg = l & 7;                // 8 row-groups x 4 rows
    const int cg = l >> 3;               // 4 col-groups x 4 cols

    const int i_loc = (tid & 255) >> 3;  // 0..31 (update threads: tid<256)
    const int lb    = tid & 7;           // 0..7
    const int h     = i0 + i_loc;
    const int b     = bt * 8 + lb;

    float s = 0.0f, s_sin = 0.0f, s_cos = 1.0f;

    __syncthreads();

    int ping = 0;
    unsigned target = 0;

    for (int t = 0; t < T_STEPS; ++t) {
        float p = 0.0f;
        if (tid < 256) p = __ldg(&d_P[((size_t)t * NH + h) * BB + b]);

        // ---- per-warp stage of this warp's V slice (4KB) into smem ----
        {
            const float4* src = (const float4*)(&d_V[ping][bt][0][0]) + w * 256;
            float4* dst = (float4*)(Vs + w * KS * CB);
            float4 tmp[8];
#pragma unroll
            for (int k = 0; k < 8; ++k) tmp[k] = __ldcg(src + l + k * 32);
#pragma unroll
            for (int k = 0; k < 8; ++k) dst[l + k * 32] = tmp[k];
        }
        __syncwarp();

        // ---- GEMM: warp K-split (64 j), thread tile 4x4, f32x2, sw-pipelined ----
        ull acc[2][4];
#pragma unroll
        for (int c = 0; c < 4; ++c) { acc[0][c] = 0ull; acc[1][c] = 0ull; }

        const float* Wp = WhT + (w * KS) * IT + rg * 4;
        const float* Vp = Vs  + (w * KS) * CB + cg * 4;

        ulonglong2 wc = *(const ulonglong2*)Wp;
        float4     vc = *(const float4*)Vp;

#pragma unroll 8
        for (int jj = 0; jj < KS; ++jj) {
            // prefetch next iteration (one-past-end lands in smem, unused)
            const ulonglong2 wn = *(const ulonglong2*)(Wp + IT);
            const float4     vn = *(const float4*)(Vp + CB);
            ull dv0, dv1, dv2, dv3;
            PACK2(dv0, vc.x, vc.x); PACK2(dv1, vc.y, vc.y);
            PACK2(dv2, vc.z, vc.z); PACK2(dv3, vc.w, vc.w);
            FMA2(acc[0][0], wc.x, dv0, acc[0][0]); FMA2(acc[1][0], wc.y, dv0, acc[1][0]);
            FMA2(acc[0][1], wc.x, dv1, acc[0][1]); FMA2(acc[1][1], wc.y, dv1, acc[1][1]);
            FMA2(acc[0][2], wc.x, dv2, acc[0][2]); FMA2(acc[1][2], wc.y, dv2, acc[1][2]);
            FMA2(acc[0][3], wc.x, dv3, acc[0][3]); FMA2(acc[1][3], wc.y, dv3, acc[1][3]);
            wc = wn; vc = vn;
            Wp += IT; Vp += CB;
        }

        // ---- cross-warp K reduction (swizzled, pad-free) ----
#pragma unroll
        for (int rp = 0; rp < 2; ++rp)
#pragma unroll
            for (int c = 0; c < 4; ++c) {
                const int RP = rg * 2 + rp, col = cg * 4 + c;
                red[(w * 16 + RP) * 16 + ((col + RP) & 15)] = acc[rp][c];
            }
        __syncthreads();
        if (tid < 256) {
            const int RP = tid >> 4, col = tid & 15;
            const int sw = (col + RP) & 15;
            ull sacc = red[RP * 16 + sw];
#pragma unroll
            for (int ww = 1; ww < NW; ++ww)
                ADD2(sacc, sacc, red[(ww * 16 + RP) * 16 + sw]);
            redF[RP * 16 + col] = sacc;
        }
        __syncthreads();

        // ---- state update for (b, h) ----
        if (tid < 256) {
            const float* rf = (const float*)redF;
            const int rp = i_loc >> 1, half = i_loc & 1;
            const float Ccos = rf[(rp * 16 + 2 * lb) * 2 + half];
            const float Csin = rf[(rp * 16 + 2 * lb + 1) * 2 + half];
            const float coup = s_sin * Ccos - s_cos * Csin;
            const float xv   = coup + p + s;
            const float k    = floorf(xv * INV_TWO_PI_F);
            float ns = fmaf(-TWO_PI_F, k, xv);
            if (ns < 0.0f) ns += TWO_PI_F;
            else if (ns >= TWO_PI_F) ns -= TWO_PI_F;
            s = ns;
            __sincosf(s, &s_sin, &s_cos);
            *(float2*)&d_V[ping ^ 1][bt][h][2 * lb] = make_float2(s_cos, s_sin);
        }
        ping ^= 1;

        // ---- group barrier: all 32 CTAs of this bt-group finished step t ----
        target += 32;
        bar_on(&g_bar4[bt * 32], target);
    }

    // ---- final state out + full-grid barrier + readout ----
    if (tid < 256) d_state[b * NH + h] = s;
    bar_on(&g_bar, GRID);

    if (cta == 0) {
        for (int pair = w; pair < BB * NO; pair += NW) {
            const int bb = pair / NO, oo = pair % NO;
            float acc = 0.0f;
            for (int hh = l; hh < NH; hh += 32)
                acc = fmaf(__ldcg(&d_state[bb * NH + hh]), W_out[(size_t)oo * NH + hh], acc);
#pragma unroll
            for (int off = 16; off; off >>= 1)
                acc += __shfl_down_sync(0xffffffffu, acc, off);
            if (l == 0) out[bb * NO + oo] = acc + b_out[oo];
        }
    }
}

extern "C" void kernel_launch(void* const* d_in, const int* in_sizes, int n_in,
                              void* d_out, int out_size) {
    const float* x     = (const float*)d_in[0];
    const float* Wi_w  = (const float*)d_in[1];
    const float* Wi_b  = (const float*)d_in[2];
    const float* Wh    = (const float*)d_in[3];
    const float* omega = (const float*)d_in[4];
    const float* W_out = (const float*)d_in[5];
    const float* b_out = (const float*)d_in[6];
    float* out = (float*)d_out;

    cudaFuncSetAttribute(scan_kernel, cudaFuncAttributeMaxDynamicSharedMemorySize, SMEM_BYTES);

    prep_kernel<<<T_STEPS * BB, 256>>>(x, Wi_w, Wi_b, omega);
    scan_kernel<<<GRID, NTH, SMEM_BYTES>>>(Wh, W_out, b_out, out);
}